// round 1
// baseline (speedup 1.0000x reference)
#include <cuda_runtime.h>
#include <cstdint>

#define GG   128
#define AA   100
#define WIN  10
#define FDIM 16
#define HD   128
#define NN   (GG*AA)   // 12800

// Scratch (device globals: no allocation allowed)
__device__ __align__(16) float g_adj[GG*AA*AA];   // normalized adjacency, 5.12 MB
__device__ __align__(16) float g_P  [NN*HD];      // X@W intermediate
__device__ __align__(16) float g_hA [NN*HD];
__device__ __align__(16) float g_hB [NN*HD];

// ---------------------------------------------------------------------------
// Kernel 1: per-group normalized adjacency
// norm_adj = D^-1/2 (1 - |corr| + I) D^-1/2
// ---------------------------------------------------------------------------
__global__ void __launch_bounds__(128) adj_kernel(const float* __restrict__ x,
                                                  float* __restrict__ adj)
{
    __shared__ float xc[AA][WIN];   // centered returns
    __shared__ float invd[AA];      // 1/sqrt(sum xc^2)
    __shared__ float dinv[AA];      // 1/sqrt(rowsum(adj))

    const int g = blockIdx.x;
    const int tid = threadIdx.x;

    if (tid < AA) {
        float r[WIN];
        float s = 0.f;
#pragma unroll
        for (int t = 0; t < WIN; t++) {
            r[t] = x[((size_t)(g*AA + tid)*WIN + t)*FDIM + (FDIM-1)];
            s += r[t];
        }
        const float mean = s * (1.0f/WIN);
        float ss = 0.f;
#pragma unroll
        for (int t = 0; t < WIN; t++) {
            float v = r[t] - mean;
            xc[tid][t] = v;
            ss += v*v;
        }
        invd[tid] = rsqrtf(ss);
    }
    __syncthreads();

    if (tid < AA) {
        float xi[WIN];
#pragma unroll
        for (int t = 0; t < WIN; t++) xi[t] = xc[tid][t];
        const float di = invd[tid];
        float rs = 0.f;
        for (int j = 0; j < AA; j++) {
            float dot = 0.f;
#pragma unroll
            for (int t = 0; t < WIN; t++) dot = fmaf(xi[t], xc[j][t], dot);
            float c = dot * di * invd[j];
            rs += 1.0f - fabsf(c);
        }
        // j==tid contributes ~0 (1-|1|); identity adds +1 on the diagonal
        dinv[tid] = rsqrtf(rs + 1.0f);
    }
    __syncthreads();

    float* ag = adj + (size_t)g*AA*AA;
    for (int e = tid; e < AA*AA; e += 128) {
        const int i = e / AA, j = e - i*AA;
        float dot = 0.f;
#pragma unroll
        for (int t = 0; t < WIN; t++) dot = fmaf(xc[i][t], xc[j][t], dot);
        float c = dot * invd[i] * invd[j];
        float a = 1.0f - fabsf(c) + (i == j ? 1.0f : 0.0f);
        ag[e] = a * dinv[i] * dinv[j];
    }
}

// ---------------------------------------------------------------------------
// Generic small matmul: C[g] = epilogue( Aop[g] (100 x K) @ Bop[(g)] (K x 128) )
// One block per group, 8 warps. Each warp: 4-row x 128-col register tile
// (4x4 accumulators per lane, lanes cover 128 cols as float4).
// A-operand: zero reuse -> straight LDG.128 (L1). B-operand: reused 25x
// within the block -> L1-resident.
// ---------------------------------------------------------------------------
template<int K, bool EPILOGUE>
__global__ void __launch_bounds__(256) mm_kernel(
    const float* __restrict__ Aop,   // [G, 100, K]
    const float* __restrict__ Bop,   // [K,128] (bStride=0) or [G,K,128]
    long bStride,
    const float* __restrict__ bias,  // [128] when EPILOGUE
    float* __restrict__ Cout)        // [G, 100, 128]
{
    const int g    = blockIdx.x;
    const int warp = threadIdx.x >> 5;
    const int lane = threadIdx.x & 31;

    const float4* A4 = reinterpret_cast<const float4*>(Aop + (size_t)g*AA*K);
    const float4* B4 = reinterpret_cast<const float4*>(Bop + (size_t)g*bStride);

    float4 bb = make_float4(0.f,0.f,0.f,0.f);
    if (EPILOGUE) bb = reinterpret_cast<const float4*>(bias)[lane];

    for (int bi = warp; bi < AA/4; bi += 8) {
        const int base = bi*4;
        float acc[4][4];
#pragma unroll
        for (int r = 0; r < 4; r++)
#pragma unroll
            for (int c = 0; c < 4; c++) acc[r][c] = 0.f;

#pragma unroll 2
        for (int j4 = 0; j4 < K/4; j4++) {
            float4 av[4];
#pragma unroll
            for (int r = 0; r < 4; r++) av[r] = A4[(base+r)*(K/4) + j4];
            const float4 b0 = B4[(4*j4+0)*32 + lane];
            const float4 b1 = B4[(4*j4+1)*32 + lane];
            const float4 b2 = B4[(4*j4+2)*32 + lane];
            const float4 b3 = B4[(4*j4+3)*32 + lane];
#pragma unroll
            for (int r = 0; r < 4; r++) {
                acc[r][0] = fmaf(av[r].x, b0.x, acc[r][0]);
                acc[r][1] = fmaf(av[r].x, b0.y, acc[r][1]);
                acc[r][2] = fmaf(av[r].x, b0.z, acc[r][2]);
                acc[r][3] = fmaf(av[r].x, b0.w, acc[r][3]);
                acc[r][0] = fmaf(av[r].y, b1.x, acc[r][0]);
                acc[r][1] = fmaf(av[r].y, b1.y, acc[r][1]);
                acc[r][2] = fmaf(av[r].y, b1.z, acc[r][2]);
                acc[r][3] = fmaf(av[r].y, b1.w, acc[r][3]);
                acc[r][0] = fmaf(av[r].z, b2.x, acc[r][0]);
                acc[r][1] = fmaf(av[r].z, b2.y, acc[r][1]);
                acc[r][2] = fmaf(av[r].z, b2.z, acc[r][2]);
                acc[r][3] = fmaf(av[r].z, b2.w, acc[r][3]);
                acc[r][0] = fmaf(av[r].w, b3.x, acc[r][0]);
                acc[r][1] = fmaf(av[r].w, b3.y, acc[r][1]);
                acc[r][2] = fmaf(av[r].w, b3.z, acc[r][2]);
                acc[r][3] = fmaf(av[r].w, b3.w, acc[r][3]);
            }
        }

        float4* outp = reinterpret_cast<float4*>(Cout + ((size_t)(g*AA + base))*HD);
#pragma unroll
        for (int r = 0; r < 4; r++) {
            float4 v;
            v.x = acc[r][0] + bb.x;
            v.y = acc[r][1] + bb.y;
            v.z = acc[r][2] + bb.z;
            v.w = acc[r][3] + bb.w;
            if (EPILOGUE) {
                v.x = fmaxf(v.x, 0.f); v.y = fmaxf(v.y, 0.f);
                v.z = fmaxf(v.z, 0.f); v.w = fmaxf(v.w, 0.f);
            }
            outp[r*32 + lane] = v;
        }
    }
}

// ---------------------------------------------------------------------------
// Kernel: fused conv1(relu) + conv2 along the feature dim, one warp per row.
// h1[c,w] = relu(cb1[c] + cw1[c,0]*h[w-1] + cw1[c,1]*h[w] + cw1[c,2]*h[w+1])
// out[w]  = cb2 + sum_c cw2[c,0]*h1[c,w-1] + cw2[c,1]*h1[c,w] + cw2[c,2]*h1[c,w+1]
// Lanes hold 4 contiguous w; halos via 2 shuffles per channel.
// ---------------------------------------------------------------------------
__global__ void __launch_bounds__(256) conv_kernel(
    const float* __restrict__ h,
    const float* __restrict__ cw1, const float* __restrict__ cb1,
    const float* __restrict__ cw2, const float* __restrict__ cb2,
    float* __restrict__ out)
{
    __shared__ float4 w1s[HD];  // {cw1_0, cw1_1, cw1_2, cb1}
    __shared__ float4 w2s[HD];  // {cw2_0, cw2_1, cw2_2, 0}

    const int tid = threadIdx.x;
    if (tid < HD) {
        w1s[tid] = make_float4(cw1[3*tid+0], cw1[3*tid+1], cw1[3*tid+2], cb1[tid]);
        w2s[tid] = make_float4(cw2[3*tid+0], cw2[3*tid+1], cw2[3*tid+2], 0.f);
    }
    __syncthreads();

    const int warp = tid >> 5, lane = tid & 31;
    const int row  = blockIdx.x*8 + warp;

    const float4 hv = reinterpret_cast<const float4*>(h + (size_t)row*HD)[lane];
    const float h0 = hv.x, h1 = hv.y, h2 = hv.z, h3 = hv.w;
    float hm1 = __shfl_up_sync(0xffffffffu, h3, 1);  if (lane == 0)  hm1 = 0.f;
    float hp1 = __shfl_down_sync(0xffffffffu, h0, 1); if (lane == 31) hp1 = 0.f;

    float acc0 = 0.f, acc1 = 0.f, acc2 = 0.f, acc3 = 0.f;

#pragma unroll 4
    for (int c = 0; c < HD; c++) {
        const float4 wa = w1s[c];
        const float4 wb = w2s[c];
        float z0 = fmaxf(fmaf(wa.x, hm1, fmaf(wa.y, h0, fmaf(wa.z, h1, wa.w))), 0.f);
        float z1 = fmaxf(fmaf(wa.x, h0,  fmaf(wa.y, h1, fmaf(wa.z, h2, wa.w))), 0.f);
        float z2 = fmaxf(fmaf(wa.x, h1,  fmaf(wa.y, h2, fmaf(wa.z, h3, wa.w))), 0.f);
        float z3 = fmaxf(fmaf(wa.x, h2,  fmaf(wa.y, h3, fmaf(wa.z, hp1, wa.w))), 0.f);

        float zm1 = __shfl_up_sync(0xffffffffu, z3, 1);  if (lane == 0)  zm1 = 0.f;
        float zp1 = __shfl_down_sync(0xffffffffu, z0, 1); if (lane == 31) zp1 = 0.f;

        acc0 = fmaf(wb.x, zm1, fmaf(wb.y, z0, fmaf(wb.z, z1, acc0)));
        acc1 = fmaf(wb.x, z0,  fmaf(wb.y, z1, fmaf(wb.z, z2, acc1)));
        acc2 = fmaf(wb.x, z1,  fmaf(wb.y, z2, fmaf(wb.z, z3, acc2)));
        acc3 = fmaf(wb.x, z2,  fmaf(wb.y, z3, fmaf(wb.z, zp1, acc3)));
    }

    const float c2 = cb2[0];
    float4 res = make_float4(acc0 + c2, acc1 + c2, acc2 + c2, acc3 + c2);
    reinterpret_cast<float4*>(out + (size_t)row*HD)[lane] = res;
}

// ---------------------------------------------------------------------------
extern "C" void kernel_launch(void* const* d_in, const int* in_sizes, int n_in,
                              void* d_out, int out_size)
{
    const float* x   = (const float*)d_in[0];
    const float* W1  = (const float*)d_in[1];
    const float* b1  = (const float*)d_in[2];
    const float* W2  = (const float*)d_in[3];
    const float* b2  = (const float*)d_in[4];
    const float* W3  = (const float*)d_in[5];
    const float* b3  = (const float*)d_in[6];
    const float* cw1 = (const float*)d_in[7];
    const float* cb1 = (const float*)d_in[8];
    const float* cw2 = (const float*)d_in[9];
    const float* cb2 = (const float*)d_in[10];
    float* out = (float*)d_out;

    float *adjp, *Pp, *hAp, *hBp;
    cudaGetSymbolAddress((void**)&adjp, g_adj);
    cudaGetSymbolAddress((void**)&Pp,   g_P);
    cudaGetSymbolAddress((void**)&hAp,  g_hA);
    cudaGetSymbolAddress((void**)&hBp,  g_hB);

    // 1) adjacency
    adj_kernel<<<GG, 128>>>(x, adjp);

    // 2) layer 1: P = x@W1 ; hA = relu(adj@P + b1)
    mm_kernel<160, false><<<GG, 256>>>(x,   W1, 0,               nullptr, Pp);
    mm_kernel<100, true ><<<GG, 256>>>(adjp, Pp, (long)AA*HD,    b1,      hAp);

    // 3) layer 2
    mm_kernel<128, false><<<GG, 256>>>(hAp, W2, 0,               nullptr, Pp);
    mm_kernel<100, true ><<<GG, 256>>>(adjp, Pp, (long)AA*HD,    b2,      hBp);

    // 4) layer 3
    mm_kernel<128, false><<<GG, 256>>>(hBp, W3, 0,               nullptr, Pp);
    mm_kernel<100, true ><<<GG, 256>>>(adjp, Pp, (long)AA*HD,    b3,      hAp);

    // 5) fused conv1(relu)+conv2
    conv_kernel<<<NN/8, 256>>>(hAp, cw1, cb1, cw2, cb2, out);
}

// round 2
// speedup vs baseline: 1.3313x; 1.3313x over previous
#include <cuda_runtime.h>
#include <cstdint>

#define GG   128
#define AA   100
#define WIN  10
#define FDIM 16
#define HD   128
#define NN   (GG*AA)   // 12800

typedef unsigned long long ull;

// ---- packed f32x2 helpers (FFMA2 path; ptxas never emits these from C++) ----
__device__ __forceinline__ ull pk2(float lo, float hi) {
    ull r; asm("mov.b64 %0, {%1,%2};" : "=l"(r) : "f"(lo), "f"(hi)); return r;
}
__device__ __forceinline__ ull fma2(ull a, ull b, ull c) {
    ull d; asm("fma.rn.f32x2 %0, %1, %2, %3;" : "=l"(d) : "l"(a), "l"(b), "l"(c)); return d;
}
__device__ __forceinline__ ull add2(ull a, ull b) {
    ull d; asm("add.rn.f32x2 %0, %1, %2;" : "=l"(d) : "l"(a), "l"(b)); return d;
}
__device__ __forceinline__ float2 upk2(ull v) {
    float lo, hi; asm("mov.b64 {%0,%1}, %2;" : "=f"(lo), "=f"(hi) : "l"(v));
    return make_float2(lo, hi);
}

// Scratch (device globals: no allocation allowed)
__device__ __align__(16) float g_adj[GG*AA*AA];
__device__ __align__(16) float g_P  [NN*HD];
__device__ __align__(16) float g_hA [NN*HD];
__device__ __align__(16) float g_hB [NN*HD];

// ---------------------------------------------------------------------------
// Kernel 1: per-group normalized adjacency
// ---------------------------------------------------------------------------
__global__ void __launch_bounds__(128) adj_kernel(const float* __restrict__ x,
                                                  float* __restrict__ adj)
{
    __shared__ float xc[AA][WIN];
    __shared__ float invd[AA];
    __shared__ float dinv[AA];

    const int g = blockIdx.x;
    const int tid = threadIdx.x;

    if (tid < AA) {
        float r[WIN];
        float s = 0.f;
#pragma unroll
        for (int t = 0; t < WIN; t++) {
            r[t] = x[((size_t)(g*AA + tid)*WIN + t)*FDIM + (FDIM-1)];
            s += r[t];
        }
        const float mean = s * (1.0f/WIN);
        float ss = 0.f;
#pragma unroll
        for (int t = 0; t < WIN; t++) {
            float v = r[t] - mean;
            xc[tid][t] = v;
            ss += v*v;
        }
        invd[tid] = rsqrtf(ss);
    }
    __syncthreads();

    if (tid < AA) {
        float xi[WIN];
#pragma unroll
        for (int t = 0; t < WIN; t++) xi[t] = xc[tid][t];
        const float di = invd[tid];
        float rs = 0.f;
        for (int j = 0; j < AA; j++) {
            float dot = 0.f;
#pragma unroll
            for (int t = 0; t < WIN; t++) dot = fmaf(xi[t], xc[j][t], dot);
            float c = dot * di * invd[j];
            rs += 1.0f - fabsf(c);
        }
        dinv[tid] = rsqrtf(rs + 1.0f);
    }
    __syncthreads();

    float* ag = adj + (size_t)g*AA*AA;
    for (int e = tid; e < AA*AA; e += 128) {
        const int i = e / AA, j = e - i*AA;
        float dot = 0.f;
#pragma unroll
        for (int t = 0; t < WIN; t++) dot = fmaf(xc[i][t], xc[j][t], dot);
        float c = dot * invd[i] * invd[j];
        float a = 1.0f - fabsf(c) + (i == j ? 1.0f : 0.0f);
        ag[e] = a * dinv[i] * dinv[j];
    }
}

// ---------------------------------------------------------------------------
// Packed small matmul. Warp-per-tile: tile = R rows x 128 cols, flat tile
// index over (group, row-tile) so the grid fills all SMs. Columns packed as
// f32x2 pairs; B rows read directly as ulonglong2 (already packed in memory).
// ---------------------------------------------------------------------------
template<int K, int R, bool EPI>
__device__ __forceinline__ void mm_tile(const float4* __restrict__ A4,
                                        const ulonglong2* __restrict__ B2,
                                        const float* __restrict__ bias,
                                        float* __restrict__ outBase, int lane)
{
    ull acc[R][2];
#pragma unroll
    for (int r = 0; r < R; r++) { acc[r][0] = 0ull; acc[r][1] = 0ull; }

#pragma unroll 1
    for (int j4 = 0; j4 < K/4; j4++) {
        const ulonglong2 q0 = B2[(4*j4+0)*32 + lane];
        const ulonglong2 q1 = B2[(4*j4+1)*32 + lane];
        const ulonglong2 q2 = B2[(4*j4+2)*32 + lane];
        const ulonglong2 q3 = B2[(4*j4+3)*32 + lane];
#pragma unroll
        for (int r = 0; r < R; r++) {
            const float4 a = A4[r*(K/4) + j4];
            const ull a0 = pk2(a.x, a.x);
            const ull a1 = pk2(a.y, a.y);
            const ull a2 = pk2(a.z, a.z);
            const ull a3 = pk2(a.w, a.w);
            acc[r][0] = fma2(a0, q0.x, acc[r][0]); acc[r][1] = fma2(a0, q0.y, acc[r][1]);
            acc[r][0] = fma2(a1, q1.x, acc[r][0]); acc[r][1] = fma2(a1, q1.y, acc[r][1]);
            acc[r][0] = fma2(a2, q2.x, acc[r][0]); acc[r][1] = fma2(a2, q2.y, acc[r][1]);
            acc[r][0] = fma2(a3, q3.x, acc[r][0]); acc[r][1] = fma2(a3, q3.y, acc[r][1]);
        }
    }

    float4 bb = make_float4(0.f, 0.f, 0.f, 0.f);
    if (EPI) bb = reinterpret_cast<const float4*>(bias)[lane];

#pragma unroll
    for (int r = 0; r < R; r++) {
        const float2 lo = upk2(acc[r][0]);
        const float2 hi = upk2(acc[r][1]);
        float4 v = make_float4(lo.x + bb.x, lo.y + bb.y, hi.x + bb.z, hi.y + bb.w);
        if (EPI) {
            v.x = fmaxf(v.x, 0.f); v.y = fmaxf(v.y, 0.f);
            v.z = fmaxf(v.z, 0.f); v.w = fmaxf(v.w, 0.f);
        }
        reinterpret_cast<float4*>(outBase + (size_t)r*HD)[lane] = v;
    }
}

#define TPG 13   // tiles per group: 12 x 8 rows + 1 x 4 rows = 100

template<int K, bool EPI>
__global__ void __launch_bounds__(128) mm_kernel(
    const float* __restrict__ Aop,   // [G, 100, K]
    const float* __restrict__ Bop,   // [K,128] (bStride=0) or [G,K,128]
    long bStride,
    const float* __restrict__ bias,
    float* __restrict__ Cout)        // [G, 100, 128]
{
    const int warp = threadIdx.x >> 5;
    const int lane = threadIdx.x & 31;
    const int t    = blockIdx.x*4 + warp;       // 0 .. GG*TPG-1
    const int g    = t / TPG;
    const int bi   = t - g*TPG;
    const int base = bi * 8;

    const float4*     A4 = reinterpret_cast<const float4*>(Aop + (size_t)g*AA*K)
                           + (size_t)base*(K/4);
    const ulonglong2* B2 = reinterpret_cast<const ulonglong2*>(Bop + (size_t)g*bStride);
    float* outBase = Cout + ((size_t)(g*AA + base))*HD;

    if (base + 8 <= AA) {
        mm_tile<K, 8, EPI>(A4, B2, bias, outBase, lane);
    } else {
        mm_tile<K, 4, EPI>(A4, B2, bias, outBase, lane);
    }
}

// ---------------------------------------------------------------------------
// Fused conv1(relu)+conv2, one warp per row. Packed f32x2 math; duplicated
// packed weights in smem; halo shuffles hoisted out of the channel loop via
// shifted accumulators T0/T1/T2; ReLU as exact 0.5*(x+|x|) with the 0.5
// folded into conv2 weights.
// ---------------------------------------------------------------------------
__global__ void __launch_bounds__(256) conv_kernel(
    const float* __restrict__ h,
    const float* __restrict__ cw1, const float* __restrict__ cb1,
    const float* __restrict__ cw2, const float* __restrict__ cb2,
    float* __restrict__ out)
{
    __shared__ ulonglong2 wpk[HD][4];

    const int tid = threadIdx.x;
    if (tid < HD) {
        const float wx = cw1[3*tid+0], wy = cw1[3*tid+1], wz = cw1[3*tid+2];
        const float wb = cb1[tid];
        const float u0 = 0.5f*cw2[3*tid+0], u1 = 0.5f*cw2[3*tid+1], u2 = 0.5f*cw2[3*tid+2];
        wpk[tid][0] = make_ulonglong2(pk2(wx, wx), pk2(wy, wy));
        wpk[tid][1] = make_ulonglong2(pk2(wz, wz), pk2(wb, wb));
        wpk[tid][2] = make_ulonglong2(pk2(u0, u0), pk2(u1, u1));
        wpk[tid][3] = make_ulonglong2(pk2(u2, u2), 0ull);
    }
    __syncthreads();

    const int warp = tid >> 5, lane = tid & 31;
    const int row  = blockIdx.x*8 + warp;

    const float4 hv = reinterpret_cast<const float4*>(h + (size_t)row*HD)[lane];
    float hm1 = __shfl_up_sync(0xffffffffu, hv.w, 1);  if (lane == 0)  hm1 = 0.f;
    float hp1 = __shfl_down_sync(0xffffffffu, hv.x, 1); if (lane == 31) hp1 = 0.f;

    const ull Pm = pk2(hm1,  hv.x);
    const ull P0 = pk2(hv.x, hv.y);
    const ull P1 = pk2(hv.y, hv.z);
    const ull P2 = pk2(hv.z, hv.w);
    const ull P3 = pk2(hv.w, hp1);

    const ull M = 0x7FFFFFFF7FFFFFFFull;   // packed fabs mask

    ull T0a = 0ull, T0b = 0ull, T1a = 0ull, T1b = 0ull, T2a = 0ull, T2b = 0ull;

#pragma unroll 4
    for (int c = 0; c < HD; c++) {
        const ulonglong2 q0 = wpk[c][0];   // (wx,wx),(wy,wy)
        const ulonglong2 q1 = wpk[c][1];   // (wz,wz),(wb,wb)
        const ulonglong2 q2 = wpk[c][2];   // (u0,u0),(u1,u1)
        const ull        q3 = wpk[c][3].x; // (u2,u2)

        // conv1 (pre-ReLU z), pairs (w0,w1) and (w2,w3)
        ull z01 = fma2(q0.x, Pm, fma2(q0.y, P0, fma2(q1.x, P1, q1.y)));
        ull z23 = fma2(q0.x, P1, fma2(q0.y, P2, fma2(q1.x, P3, q1.y)));

        // 2*relu(z) = z + |z|  (exact); 0.5 pre-folded into u-weights
        z01 = add2(z01, z01 & M);
        z23 = add2(z23, z23 & M);

        // conv2 shifted accumulators
        T0a = fma2(q2.x, z01, T0a);  T0b = fma2(q2.x, z23, T0b);
        T1a = fma2(q2.y, z01, T1a);  T1b = fma2(q2.y, z23, T1b);
        T2a = fma2(q3,   z01, T2a);  T2b = fma2(q3,   z23, T2b);
    }

    const float2 t0a = upk2(T0a), t0b = upk2(T0b);
    const float2 t1a = upk2(T1a), t1b = upk2(T1b);
    const float2 t2a = upk2(T2a), t2b = upk2(T2b);

    // out[w] = T0[w-1] + T1[w] + T2[w+1] + cb2  (zero beyond edges)
    float t0m = __shfl_up_sync(0xffffffffu, t0b.y, 1);  if (lane == 0)  t0m = 0.f;
    float t2p = __shfl_down_sync(0xffffffffu, t2a.x, 1); if (lane == 31) t2p = 0.f;

    const float c2 = cb2[0];
    float4 res;
    res.x = t0m   + t1a.x + t2a.y + c2;
    res.y = t0a.x + t1a.y + t2b.x + c2;
    res.z = t0a.y + t1b.x + t2b.y + c2;
    res.w = t0b.x + t1b.y + t2p   + c2;
    reinterpret_cast<float4*>(out + (size_t)row*HD)[lane] = res;
}

// ---------------------------------------------------------------------------
extern "C" void kernel_launch(void* const* d_in, const int* in_sizes, int n_in,
                              void* d_out, int out_size)
{
    const float* x   = (const float*)d_in[0];
    const float* W1  = (const float*)d_in[1];
    const float* b1  = (const float*)d_in[2];
    const float* W2  = (const float*)d_in[3];
    const float* b2  = (const float*)d_in[4];
    const float* W3  = (const float*)d_in[5];
    const float* b3  = (const float*)d_in[6];
    const float* cw1 = (const float*)d_in[7];
    const float* cb1 = (const float*)d_in[8];
    const float* cw2 = (const float*)d_in[9];
    const float* cb2 = (const float*)d_in[10];
    float* out = (float*)d_out;

    float *adjp, *Pp, *hAp, *hBp;
    cudaGetSymbolAddress((void**)&adjp, g_adj);
    cudaGetSymbolAddress((void**)&Pp,   g_P);
    cudaGetSymbolAddress((void**)&hAp,  g_hA);
    cudaGetSymbolAddress((void**)&hBp,  g_hB);

    const int MMBLK = (GG*TPG)/4;   // 416 blocks of 128 threads (4 warp-tiles)

    // 1) adjacency
    adj_kernel<<<GG, 128>>>(x, adjp);

    // 2) layer 1: P = x@W1 ; hA = relu(adj@P + b1)
    mm_kernel<160, false><<<MMBLK, 128>>>(x,    W1, 0,            nullptr, Pp);
    mm_kernel<100, true ><<<MMBLK, 128>>>(adjp, Pp, (long)AA*HD,  b1,      hAp);

    // 3) layer 2
    mm_kernel<128, false><<<MMBLK, 128>>>(hAp,  W2, 0,            nullptr, Pp);
    mm_kernel<100, true ><<<MMBLK, 128>>>(adjp, Pp, (long)AA*HD,  b2,      hBp);

    // 4) layer 3
    mm_kernel<128, false><<<MMBLK, 128>>>(hBp,  W3, 0,            nullptr, Pp);
    mm_kernel<100, true ><<<MMBLK, 128>>>(adjp, Pp, (long)AA*HD,  b3,      hAp);

    // 5) fused conv1(relu)+conv2
    conv_kernel<<<NN/8, 256>>>(hAp, cw1, cb1, cw2, cb2, out);
}

// round 3
// speedup vs baseline: 1.6754x; 1.2585x over previous
#include <cuda_runtime.h>
#include <cstdint>

#define GG   128
#define AA   100
#define WIN  10
#define FDIM 16
#define HD   128
#define NN   (GG*AA)

typedef unsigned long long ull;

// ---- packed f32x2 helpers ----
__device__ __forceinline__ ull pk2(float lo, float hi) {
    ull r; asm("mov.b64 %0, {%1,%2};" : "=l"(r) : "f"(lo), "f"(hi)); return r;
}
__device__ __forceinline__ ull fma2(ull a, ull b, ull c) {
    ull d; asm("fma.rn.f32x2 %0, %1, %2, %3;" : "=l"(d) : "l"(a), "l"(b), "l"(c)); return d;
}
__device__ __forceinline__ ull add2(ull a, ull b) {
    ull d; asm("add.rn.f32x2 %0, %1, %2;" : "=l"(d) : "l"(a), "l"(b)); return d;
}
__device__ __forceinline__ float2 upk2(ull v) {
    float lo, hi; asm("mov.b64 {%0,%1}, %2;" : "=f"(lo), "=f"(hi) : "l"(v));
    return make_float2(lo, hi);
}

// ---------------------------------------------------------------------------
// GEMM warp tile: R rows x 128 cols, K contraction. A rows (gmem or smem),
// B [K,128] viewed as packed ulonglong2, C -> smem (float4 stores).
// ---------------------------------------------------------------------------
template<int K, int R, bool RELU>
__device__ __forceinline__ void gemm_tile(const float* __restrict__ A, int aStride4,
                                          const ulonglong2* __restrict__ B2,
                                          const float* __restrict__ bias,
                                          float* __restrict__ Cs, int lane)
{
    const float4* A4 = reinterpret_cast<const float4*>(A);
    ull acc[R][2];
#pragma unroll
    for (int r = 0; r < R; r++) { acc[r][0] = 0ull; acc[r][1] = 0ull; }

#pragma unroll 2
    for (int j4 = 0; j4 < K/4; j4++) {
        const ulonglong2 q0 = B2[(4*j4+0)*32 + lane];
        const ulonglong2 q1 = B2[(4*j4+1)*32 + lane];
        const ulonglong2 q2 = B2[(4*j4+2)*32 + lane];
        const ulonglong2 q3 = B2[(4*j4+3)*32 + lane];
#pragma unroll
        for (int r = 0; r < R; r++) {
            const float4 a = A4[r*aStride4 + j4];
            const ull a0 = pk2(a.x, a.x);
            const ull a1 = pk2(a.y, a.y);
            const ull a2 = pk2(a.z, a.z);
            const ull a3 = pk2(a.w, a.w);
            acc[r][0] = fma2(a0, q0.x, acc[r][0]); acc[r][1] = fma2(a0, q0.y, acc[r][1]);
            acc[r][0] = fma2(a1, q1.x, acc[r][0]); acc[r][1] = fma2(a1, q1.y, acc[r][1]);
            acc[r][0] = fma2(a2, q2.x, acc[r][0]); acc[r][1] = fma2(a2, q2.y, acc[r][1]);
            acc[r][0] = fma2(a3, q3.x, acc[r][0]); acc[r][1] = fma2(a3, q3.y, acc[r][1]);
        }
    }

    float4 bb = make_float4(0.f, 0.f, 0.f, 0.f);
    if (RELU) bb = reinterpret_cast<const float4*>(bias)[lane];

#pragma unroll
    for (int r = 0; r < R; r++) {
        const float2 lo = upk2(acc[r][0]);
        const float2 hi = upk2(acc[r][1]);
        float4 v = make_float4(lo.x + bb.x, lo.y + bb.y, hi.x + bb.z, hi.y + bb.w);
        if (RELU) {
            v.x = fmaxf(v.x, 0.f); v.y = fmaxf(v.y, 0.f);
            v.z = fmaxf(v.z, 0.f); v.w = fmaxf(v.w, 0.f);
        }
        reinterpret_cast<float4*>(Cs + (size_t)r*HD)[lane] = v;
    }
}

template<int K, bool RELU>
__device__ __forceinline__ void gemm_phase(const float* __restrict__ Abase, int aStrideF,
                                           const float* __restrict__ B,
                                           const float* __restrict__ bias,
                                           float* __restrict__ Cs, int warp, int lane)
{
    const ulonglong2* B2 = reinterpret_cast<const ulonglong2*>(B);
    int start, R;
    if (warp < 4) { start = warp*7;          R = 7; }
    else          { start = 28 + (warp-4)*6; R = 6; }
    const float* A = Abase + (size_t)start*aStrideF;
    float* C = Cs + (size_t)start*HD;
    if (R == 7) gemm_tile<K, 7, RELU>(A, aStrideF/4, B2, bias, C, lane);
    else        gemm_tile<K, 6, RELU>(A, aStrideF/4, B2, bias, C, lane);
}

// ---------------------------------------------------------------------------
// One block per group: adjacency -> 3 GCN layers -> fused conv, all in smem.
// ---------------------------------------------------------------------------
__global__ void __launch_bounds__(512, 1) fused_kernel(
    const float* __restrict__ x,
    const float* __restrict__ W1, const float* __restrict__ b1,
    const float* __restrict__ W2, const float* __restrict__ b2,
    const float* __restrict__ W3, const float* __restrict__ b3,
    const float* __restrict__ cw1, const float* __restrict__ cb1,
    const float* __restrict__ cw2, const float* __restrict__ cb2,
    float* __restrict__ out)
{
    extern __shared__ float sm[];
    float*      s_adj  = sm;                          // 100*100
    float*      s_buf0 = s_adj  + AA*AA;              // 100*128
    float*      s_buf1 = s_buf0 + AA*HD;              // 100*128
    ulonglong2* s_wc   = reinterpret_cast<ulonglong2*>(s_buf1 + AA*HD); // 128*4

    __shared__ float xc[AA][WIN];
    __shared__ float invd[AA];
    __shared__ float dinv[AA];

    const int g    = blockIdx.x;
    const int tid  = threadIdx.x;
    const int warp = tid >> 5;
    const int lane = tid & 31;

    // ---- Phase 0: adjacency prep + conv-weight packing ----
    if (tid < AA) {
        float r[WIN]; float s = 0.f;
#pragma unroll
        for (int t = 0; t < WIN; t++) {
            r[t] = x[((size_t)(g*AA + tid)*WIN + t)*FDIM + (FDIM-1)];
            s += r[t];
        }
        const float mean = s * (1.0f/WIN);
        float ss = 0.f;
#pragma unroll
        for (int t = 0; t < WIN; t++) {
            float v = r[t] - mean;
            xc[tid][t] = v;
            ss += v*v;
        }
        invd[tid] = rsqrtf(ss);
    }
    if (tid >= 256 && tid < 256 + HD) {
        const int c = tid - 256;
        const float wx = cw1[3*c+0], wy = cw1[3*c+1], wz = cw1[3*c+2];
        const float wb = cb1[c];
        const float u0 = 0.5f*cw2[3*c+0], u1 = 0.5f*cw2[3*c+1], u2 = 0.5f*cw2[3*c+2];
        s_wc[c*4+0] = make_ulonglong2(pk2(wx, wx), pk2(wy, wy));
        s_wc[c*4+1] = make_ulonglong2(pk2(wz, wz), pk2(wb, wb));
        s_wc[c*4+2] = make_ulonglong2(pk2(u0, u0), pk2(u1, u1));
        s_wc[c*4+3] = make_ulonglong2(pk2(u2, u2), 0ull);
    }
    __syncthreads();

    if (tid < AA) {
        float xi[WIN];
#pragma unroll
        for (int t = 0; t < WIN; t++) xi[t] = xc[tid][t];
        const float di = invd[tid];
        float rs = 0.f;
#pragma unroll 2
        for (int j = 0; j < AA; j++) {
            float dot = 0.f;
#pragma unroll
            for (int t = 0; t < WIN; t++) dot = fmaf(xi[t], xc[j][t], dot);
            float c = dot * di * invd[j];
            rs += 1.0f - fabsf(c);
        }
        dinv[tid] = rsqrtf(rs + 1.0f);
    }
    __syncthreads();

    for (int e = tid; e < AA*AA; e += 512) {
        const int i = e / AA, j = e - i*AA;
        float dot = 0.f;
#pragma unroll
        for (int t = 0; t < WIN; t++) dot = fmaf(xc[i][t], xc[j][t], dot);
        float c = dot * invd[i] * invd[j];
        float a = 1.0f - fabsf(c) + (i == j ? 1.0f : 0.0f);
        s_adj[e] = a * dinv[i] * dinv[j];
    }
    __syncthreads();

    // ---- GCN layers (activations live in smem) ----
    const float* xg = x + (size_t)g*AA*(WIN*FDIM);

    gemm_phase<WIN*FDIM, false>(xg,    WIN*FDIM, W1,     nullptr, s_buf0, warp, lane);
    __syncthreads();
    gemm_phase<AA,       true >(s_adj, AA,       s_buf0, b1,      s_buf1, warp, lane);
    __syncthreads();
    gemm_phase<HD,       false>(s_buf1, HD,      W2,     nullptr, s_buf0, warp, lane);
    __syncthreads();
    gemm_phase<AA,       true >(s_adj, AA,       s_buf0, b2,      s_buf1, warp, lane);
    __syncthreads();
    gemm_phase<HD,       false>(s_buf1, HD,      W3,     nullptr, s_buf0, warp, lane);
    __syncthreads();
    gemm_phase<AA,       true >(s_adj, AA,       s_buf0, b3,      s_buf1, warp, lane);
    __syncthreads();

    // ---- Fused conv1(relu)+conv2: one warp per row, packed f32x2 ----
    const float c2 = cb2[0];
    const ull M = 0x7FFFFFFF7FFFFFFFull;

    for (int row = warp; row < AA; row += 16) {
        const float4 hv = reinterpret_cast<const float4*>(s_buf1 + (size_t)row*HD)[lane];
        float hm1 = __shfl_up_sync(0xffffffffu, hv.w, 1);  if (lane == 0)  hm1 = 0.f;
        float hp1 = __shfl_down_sync(0xffffffffu, hv.x, 1); if (lane == 31) hp1 = 0.f;

        const ull Pm = pk2(hm1,  hv.x);
        const ull P0 = pk2(hv.x, hv.y);
        const ull P1 = pk2(hv.y, hv.z);
        const ull P2 = pk2(hv.z, hv.w);
        const ull P3 = pk2(hv.w, hp1);

        ull T0a = 0ull, T0b = 0ull, T1a = 0ull, T1b = 0ull, T2a = 0ull, T2b = 0ull;

#pragma unroll 4
        for (int c = 0; c < HD; c++) {
            const ulonglong2 q0 = s_wc[c*4+0];
            const ulonglong2 q1 = s_wc[c*4+1];
            const ulonglong2 q2 = s_wc[c*4+2];
            const ull        q3 = s_wc[c*4+3].x;

            ull z01 = fma2(q0.x, Pm, fma2(q0.y, P0, fma2(q1.x, P1, q1.y)));
            ull z23 = fma2(q0.x, P1, fma2(q0.y, P2, fma2(q1.x, P3, q1.y)));

            z01 = add2(z01, z01 & M);   // 2*relu(z), 0.5 folded into u-weights
            z23 = add2(z23, z23 & M);

            T0a = fma2(q2.x, z01, T0a);  T0b = fma2(q2.x, z23, T0b);
            T1a = fma2(q2.y, z01, T1a);  T1b = fma2(q2.y, z23, T1b);
            T2a = fma2(q3,   z01, T2a);  T2b = fma2(q3,   z23, T2b);
        }

        const float2 t0a = upk2(T0a), t0b = upk2(T0b);
        const float2 t1a = upk2(T1a), t1b = upk2(T1b);
        const float2 t2a = upk2(T2a), t2b = upk2(T2b);

        float t0m = __shfl_up_sync(0xffffffffu, t0b.y, 1);  if (lane == 0)  t0m = 0.f;
        float t2p = __shfl_down_sync(0xffffffffu, t2a.x, 1); if (lane == 31) t2p = 0.f;

        float4 res;
        res.x = t0m   + t1a.x + t2a.y + c2;
        res.y = t0a.x + t1a.y + t2b.x + c2;
        res.z = t0a.y + t1b.x + t2b.y + c2;
        res.w = t0b.x + t1b.y + t2p   + c2;
        reinterpret_cast<float4*>(out + ((size_t)(g*AA + row))*HD)[lane] = res;
    }
}

// ---------------------------------------------------------------------------
extern "C" void kernel_launch(void* const* d_in, const int* in_sizes, int n_in,
                              void* d_out, int out_size)
{
    const float* x   = (const float*)d_in[0];
    const float* W1  = (const float*)d_in[1];
    const float* b1  = (const float*)d_in[2];
    const float* W2  = (const float*)d_in[3];
    const float* b2  = (const float*)d_in[4];
    const float* W3  = (const float*)d_in[5];
    const float* b3  = (const float*)d_in[6];
    const float* cw1 = (const float*)d_in[7];
    const float* cb1 = (const float*)d_in[8];
    const float* cw2 = (const float*)d_in[9];
    const float* cb2 = (const float*)d_in[10];
    float* out = (float*)d_out;

    const int SMEM = (AA*AA + 2*AA*HD) * (int)sizeof(float) + HD*4*(int)sizeof(ulonglong2);
    cudaFuncSetAttribute(fused_kernel, cudaFuncAttributeMaxDynamicSharedMemorySize, SMEM);

    fused_kernel<<<GG, 512, SMEM>>>(x, W1, b1, W2, b2, W3, b3,
                                    cw1, cb1, cw2, cb2, out);
}